// round 15
// baseline (speedup 1.0000x reference)
#include <cuda_runtime.h>
#include <cuda_bf16.h>
#include <cstdint>

#define N_NODES 50000
#define HID     256
#define NH      (N_NODES * HID)
#define MAX_E   2000000
#define NB_SCAN 49                      // ceil(50000/1024)
#define NBLK_M  782                     // ceil(50000/64)
#define CONV_BLKS 384                   // 3*32768/256

// ---------------- scratch (static device globals; no allocation) ------------
__device__ float g_buf1[NH];            // t = A@x, later p = A@h
__device__ float g_buf2[NH];            // h
__device__ float g_dinv[N_NODES];
__device__ int   g_deg[N_NODES];
__device__ int   g_rowptr[N_NODES + 1];
__device__ int   g_cur[N_NODES];
__device__ int   g_col[MAX_E];
__device__ int   g_bsum[NB_SCAN];
// weight images: per weight 128 kpairs x 256 cols, uint32 = 2 packed bf16 (k,k+1)
// column index pre-swizzled with n ^ ((kp&3)<<3)
__device__ uint32_t g_Bh[3 * 32768];
__device__ uint32_t g_Bl[3 * 32768];

// ---------------- bf16 pack helper -------------------------------------------
__device__ __forceinline__ uint32_t pack2bf16(float a, float b) {
    return (uint32_t)__bfloat16_as_ushort(__float2bfloat16(a))
         | ((uint32_t)__bfloat16_as_ushort(__float2bfloat16(b)) << 16);
}

// ---------------- merged: weight conversion + degree count -------------------
__global__ void k_count_conv(const int* __restrict__ ei, int E,
                             const float* __restrict__ W1,
                             const float* __restrict__ Wmu,
                             const float* __restrict__ Wls) {
    if (blockIdx.x < CONV_BLKS) {
        int idx = blockIdx.x * 256 + threadIdx.x;   // 3 * 32768 threads
        int w = idx >> 15;
        int e = idx & 32767;                        // kp*256 + n
        int kp = e >> 8, n = e & 255;
        const float* W = (w == 0) ? W1 : (w == 1) ? Wmu : Wls;
        float v0 = W[(2 * kp) * 256 + n];
        float v1 = W[(2 * kp + 1) * 256 + n];
        __nv_bfloat16 h0 = __float2bfloat16(v0);
        __nv_bfloat16 h1 = __float2bfloat16(v1);
        int ns = n ^ ((kp & 3) << 3);
        g_Bh[w * 32768 + kp * 256 + ns] =
            (uint32_t)__bfloat16_as_ushort(h0)
            | ((uint32_t)__bfloat16_as_ushort(h1) << 16);
        g_Bl[w * 32768 + kp * 256 + ns] =
            pack2bf16(v0 - __bfloat162float(h0), v1 - __bfloat162float(h1));
    } else {
        int i = (blockIdx.x - CONV_BLKS) * 256 + threadIdx.x;
        if (i < E) atomicAdd(&g_deg[ei[E + i]], 1);
    }
}

// ---------------- scan phase 1 ------------------------------------------------
__global__ void __launch_bounds__(1024) k_scan1() {
    __shared__ int sh[1024];
    int tid = threadIdx.x;
    int i = blockIdx.x * 1024 + tid;
    int v = (i < N_NODES) ? g_deg[i] : 0;
    if (i < N_NODES) g_dinv[i] = rsqrtf((float)(v + 1));   // +1 self loop
    sh[tid] = v;
    __syncthreads();
#pragma unroll
    for (int off = 1; off < 1024; off <<= 1) {
        int t = (tid >= off) ? sh[tid - off] : 0;
        __syncthreads();
        sh[tid] += t;
        __syncthreads();
    }
    if (i < N_NODES) g_rowptr[i] = sh[tid] - v;
    if (tid == 1023) g_bsum[blockIdx.x] = sh[1023];
}

// ---------------- scan phase 2 ------------------------------------------------
__global__ void __launch_bounds__(1024) k_scan2(int E) {
    __shared__ int pf[NB_SCAN];
    int tid = threadIdx.x;
    if (tid == 0) {
        int run = 0;
#pragma unroll
        for (int b = 0; b < NB_SCAN; b++) { pf[b] = run; run += g_bsum[b]; }
    }
    __syncthreads();
    int i = blockIdx.x * 1024 + tid;
    if (i < N_NODES) {
        int r = g_rowptr[i] + pf[blockIdx.x];
        g_rowptr[i] = r;
        g_cur[i] = r;
    }
    if (blockIdx.x == 0 && tid == 0) g_rowptr[N_NODES] = E;
}

__global__ void k_fill(const int* __restrict__ ei, int E) {
    int e = blockIdx.x * blockDim.x + threadIdx.x;
    if (e < E) {
        int d = ei[E + e];
        int pos = atomicAdd(&g_cur[d], 1);
        g_col[pos] = ei[e];
    }
}

// ---------------- CSR SpMM, column-split: 2 warps per node --------------------
// warp covers 128 columns (one float4 per lane); node = blockIdx*4 + (w>>1)
__global__ void __launch_bounds__(256) k_spmm_csr(const float* __restrict__ X,
                                                  float* __restrict__ Y) {
    int w = threadIdx.x >> 5;                  // 0..7
    int node = blockIdx.x * 4 + (w >> 1);
    int half = w & 1;
    int lane = threadIdx.x & 31;
    if (node >= N_NODES) return;
    const float4* X4 = (const float4*)X;
    float4* Y4 = (float4*)Y;
    int off = half * 32 + lane;                // float4 index 0..63

    float4 s = make_float4(0.f, 0.f, 0.f, 0.f);
    int beg = g_rowptr[node];
    int end = g_rowptr[node + 1];

    int e = beg;
    for (; e + 2 <= end; e += 2) {
        int sa = __ldg(&g_col[e]);
        int sb = __ldg(&g_col[e + 1]);
        float wa = g_dinv[sa];
        float wb = g_dinv[sb];
        float4 a = __ldg(X4 + (size_t)sa * 64 + off);
        float4 b = __ldg(X4 + (size_t)sb * 64 + off);
        s.x += wa * a.x + wb * b.x;
        s.y += wa * a.y + wb * b.y;
        s.z += wa * a.z + wb * b.z;
        s.w += wa * a.w + wb * b.w;
    }
    if (e < end) {
        int sa = __ldg(&g_col[e]);
        float wa = g_dinv[sa];
        float4 a = __ldg(X4 + (size_t)sa * 64 + off);
        s.x += wa * a.x; s.y += wa * a.y; s.z += wa * a.z; s.w += wa * a.w;
    }

    float dd = g_dinv[node];
    float dd2 = dd * dd;
    float4 x0 = __ldg(X4 + (size_t)node * 64 + off);
    float4 o;
    o.x = dd * s.x + dd2 * x0.x;
    o.y = dd * s.y + dd2 * x0.y;
    o.z = dd * s.z + dd2 * x0.z;
    o.w = dd * s.w + dd2 * x0.w;
    Y4[(size_t)node * 64 + off] = o;
}

// ---------------- threefry2x32 (JAX-exact) ----------------------------------
__device__ __forceinline__ uint32_t tf_rotl(uint32_t v, int s) {
    return (v << s) | (v >> (32 - s));
}

__device__ __forceinline__ uint2 threefry2x32(uint32_t k0, uint32_t k1,
                                              uint32_t x0, uint32_t x1) {
    uint32_t ks2 = k0 ^ k1 ^ 0x1BD11BDAu;
    x0 += k0; x1 += k1;
#define TF_R(r) { x0 += x1; x1 = tf_rotl(x1, r); x1 ^= x0; }
    TF_R(13) TF_R(15) TF_R(26) TF_R(6)   x0 += k1;  x1 += ks2 + 1u;
    TF_R(17) TF_R(29) TF_R(16) TF_R(24)  x0 += ks2; x1 += k0 + 2u;
    TF_R(13) TF_R(15) TF_R(26) TF_R(6)   x0 += k0;  x1 += k1 + 3u;
    TF_R(17) TF_R(29) TF_R(16) TF_R(24)  x0 += k1;  x1 += ks2 + 4u;
    TF_R(13) TF_R(15) TF_R(26) TF_R(6)   x0 += ks2; x1 += k0 + 5u;
#undef TF_R
    return make_uint2(x0, x1);
}

__device__ __forceinline__ float bits_to_eps(uint32_t bits) {
    float u01 = __uint_as_float((bits >> 9) | 0x3f800000u) - 1.0f;
    const float lo = __uint_as_float(0xBF7FFFFFu);
    const float span = 1.0f - lo;
    float v = __fadd_rn(__fmul_rn(u01, span), lo);
    v = fmaxf(lo, v);
    return 1.41421356f * erfinvf(v);
}

// ---------------- mma.sync m16n8k16 bf16 wrapper ------------------------------
__device__ __forceinline__ void mma16816(float* d, const uint32_t* a,
                                         uint32_t b0, uint32_t b1) {
    asm volatile(
        "mma.sync.aligned.m16n8k16.row.col.f32.bf16.bf16.f32 "
        "{%0,%1,%2,%3}, {%4,%5,%6,%7}, {%8,%9}, {%0,%1,%2,%3};"
        : "+f"(d[0]), "+f"(d[1]), "+f"(d[2]), "+f"(d[3])
        : "r"(a[0]), "r"(a[1]), "r"(a[2]), "r"(a[3]), "r"(b0), "r"(b1));
}

#define SMEM_MMA 82944

// ---------------- tensor-core GEMM (single weight, relu) — R11 proven ---------
__global__ void __launch_bounds__(256, 2)
k_gemm_mma(const float* __restrict__ A, int M,
           const uint32_t* __restrict__ Bh, const uint32_t* __restrict__ Bl,
           const float* __restrict__ bias, float* __restrict__ C) {
    extern __shared__ char smem[];
    float*    sBias = (float*)smem;
    uint32_t* sAh = (uint32_t*)(smem + 1024);
    uint32_t* sAl = (uint32_t*)(smem + 9216);
    uint32_t* sBh = (uint32_t*)(smem + 17408);
    uint32_t* sBl = (uint32_t*)(smem + 50176);

    int tid = threadIdx.x;
    int l = tid & 31;
    int w = tid >> 5;
    int wm = w >> 2;
    int wn = w & 3;
    int rowBase = blockIdx.x * 64;

    sBias[tid] = bias[tid];

    float acc[2][8][4];
#pragma unroll
    for (int mt = 0; mt < 2; mt++)
#pragma unroll
        for (int nt = 0; nt < 8; nt++)
#pragma unroll
            for (int r = 0; r < 4; r++) acc[mt][nt][r] = 0.f;

    int arow = tid & 63;
    int kseg = tid >> 6;
    int grow = rowBase + arow;
    bool aok = grow < M;
    const float4* abase = (const float4*)(A + (size_t)grow * 256 + kseg * 16);

    float4 f[4];
    if (aok) {
        f[0] = __ldg(abase + 0); f[1] = __ldg(abase + 1);
        f[2] = __ldg(abase + 2); f[3] = __ldg(abase + 3);
    } else {
        f[0] = f[1] = f[2] = f[3] = make_float4(0.f, 0.f, 0.f, 0.f);
    }

    for (int c = 0; c < 4; c++) {
        __syncthreads();
        {
            const float* fv = (const float*)f;
#pragma unroll
            for (int i = 0; i < 8; i++) {
                int kp = kseg * 8 + i;
                float v0 = fv[2 * i], v1 = fv[2 * i + 1];
                __nv_bfloat16 h0 = __float2bfloat16(v0);
                __nv_bfloat16 h1 = __float2bfloat16(v1);
                uint32_t hp = (uint32_t)__bfloat16_as_ushort(h0)
                            | ((uint32_t)__bfloat16_as_ushort(h1) << 16);
                uint32_t lp = pack2bf16(v0 - __bfloat162float(h0),
                                        v1 - __bfloat162float(h1));
                int sr = arow ^ ((kp & 3) << 3);
                sAh[kp * 64 + sr] = hp;
                sAl[kp * 64 + sr] = lp;
            }
        }
        {
            const uint4* gh = (const uint4*)(Bh + c * 8192);
            const uint4* gl = (const uint4*)(Bl + c * 8192);
            uint4* dh = (uint4*)sBh;
            uint4* dl = (uint4*)sBl;
#pragma unroll
            for (int i = 0; i < 8; i++) {
                dh[tid + i * 256] = __ldg(gh + tid + i * 256);
                dl[tid + i * 256] = __ldg(gl + tid + i * 256);
            }
        }
        __syncthreads();

        if (c < 3 && aok) {
            const float4* pn = abase + (c + 1) * 16;
            f[0] = __ldg(pn + 0); f[1] = __ldg(pn + 1);
            f[2] = __ldg(pn + 2); f[3] = __ldg(pn + 3);
        }

#pragma unroll
        for (int ks = 0; ks < 4; ks++) {
            int kp0 = ks * 8 + (l & 3);
            int sw = (l & 3) << 3;
            uint32_t ah[2][4], al2[2][4];
#pragma unroll
            for (int mt = 0; mt < 2; mt++) {
                int r0 = wm * 32 + mt * 16 + (l >> 2);
                int i00 = kp0 * 64 + (r0 ^ sw);
                int i01 = kp0 * 64 + ((r0 + 8) ^ sw);
                int i10 = (kp0 + 4) * 64 + (r0 ^ sw);
                int i11 = (kp0 + 4) * 64 + ((r0 + 8) ^ sw);
                ah[mt][0] = sAh[i00]; ah[mt][1] = sAh[i01];
                ah[mt][2] = sAh[i10]; ah[mt][3] = sAh[i11];
                al2[mt][0] = sAl[i00]; al2[mt][1] = sAl[i01];
                al2[mt][2] = sAl[i10]; al2[mt][3] = sAl[i11];
            }
#pragma unroll
            for (int nt = 0; nt < 8; nt++) {
                int nc = wn * 64 + nt * 8 + (l >> 2);
                int nsw = nc ^ sw;
                uint32_t bh0 = sBh[kp0 * 256 + nsw];
                uint32_t bh1 = sBh[(kp0 + 4) * 256 + nsw];
                uint32_t bl0 = sBl[kp0 * 256 + nsw];
                uint32_t bl1 = sBl[(kp0 + 4) * 256 + nsw];
#pragma unroll
                for (int mt = 0; mt < 2; mt++) {
                    mma16816(acc[mt][nt], ah[mt], bh0, bh1);
                    mma16816(acc[mt][nt], ah[mt], bl0, bl1);
                    mma16816(acc[mt][nt], al2[mt], bh0, bh1);
                }
            }
        }
    }

#pragma unroll
    for (int mt = 0; mt < 2; mt++) {
        int r = rowBase + wm * 32 + mt * 16 + (l >> 2);
#pragma unroll
        for (int nt = 0; nt < 8; nt++) {
            int colb = wn * 64 + nt * 8 + 2 * (l & 3);
            float b0v = sBias[colb], b1v = sBias[colb + 1];
#pragma unroll
            for (int half = 0; half < 2; half++) {
                int rr = r + half * 8;
                if (rr >= M) continue;
                float v0 = fmaxf(acc[mt][nt][half * 2 + 0] + b0v, 0.f);
                float v1 = fmaxf(acc[mt][nt][half * 2 + 1] + b1v, 0.f);
                *(float2*)(C + (size_t)rr * 256 + colb) = make_float2(v0, v1);
            }
        }
    }
}

// ---------------- dual column-split GEMM: mu & ls & z (R14 proven) -------------
__global__ void __launch_bounds__(256, 2)
k_gemm_dual2(const float* __restrict__ A, int M,
             const uint32_t* __restrict__ Bh0, const uint32_t* __restrict__ Bl0,
             const float* __restrict__ bias0,
             const uint32_t* __restrict__ Bh1, const uint32_t* __restrict__ Bl1,
             const float* __restrict__ bias1,
             float* __restrict__ Cmu, float* __restrict__ Cls,
             float* __restrict__ zOut) {
    extern __shared__ char smem[];
    float*    sB0 = (float*)smem;
    float*    sB1 = (float*)(smem + 512);
    uint32_t* sAh = (uint32_t*)(smem + 1024);
    uint32_t* sAl = (uint32_t*)(smem + 9216);
    uint32_t* sBh0 = (uint32_t*)(smem + 17408);
    uint32_t* sBl0 = (uint32_t*)(smem + 33792);
    uint32_t* sBh1 = (uint32_t*)(smem + 50176);
    uint32_t* sBl1 = (uint32_t*)(smem + 66560);

    int tid = threadIdx.x;
    int l = tid & 31;
    int w = tid >> 5;
    int wm = w >> 2;
    int wn = w & 3;
    int nb = blockIdx.x >> 1;
    int hf = blockIdx.x & 1;
    int rowBase = nb * 64;
    int colOff = hf * 128;

    if (tid < 128) {
        sB0[tid] = bias0[colOff + tid];
        sB1[tid] = bias1[colOff + tid];
    }

    float acc0[2][4][4], acc1[2][4][4];
#pragma unroll
    for (int mt = 0; mt < 2; mt++)
#pragma unroll
        for (int nt = 0; nt < 4; nt++)
#pragma unroll
            for (int r = 0; r < 4; r++) { acc0[mt][nt][r] = 0.f; acc1[mt][nt][r] = 0.f; }

    int arow = tid & 63;
    int kseg = tid >> 6;
    int grow = rowBase + arow;
    bool aok = grow < M;
    const float4* abase = (const float4*)(A + (size_t)grow * 256 + kseg * 16);

    float4 f[4];
    if (aok) {
        f[0] = __ldg(abase + 0); f[1] = __ldg(abase + 1);
        f[2] = __ldg(abase + 2); f[3] = __ldg(abase + 3);
    } else {
        f[0] = f[1] = f[2] = f[3] = make_float4(0.f, 0.f, 0.f, 0.f);
    }

    for (int c = 0; c < 4; c++) {
        __syncthreads();
        {
            const float* fv = (const float*)f;
#pragma unroll
            for (int i = 0; i < 8; i++) {
                int kp = kseg * 8 + i;
                float v0 = fv[2 * i], v1 = fv[2 * i + 1];
                __nv_bfloat16 h0 = __float2bfloat16(v0);
                __nv_bfloat16 h1 = __float2bfloat16(v1);
                uint32_t hp = (uint32_t)__bfloat16_as_ushort(h0)
                            | ((uint32_t)__bfloat16_as_ushort(h1) << 16);
                uint32_t lp = pack2bf16(v0 - __bfloat162float(h0),
                                        v1 - __bfloat162float(h1));
                int sr = arow ^ ((kp & 3) << 3);
                sAh[kp * 64 + sr] = hp;
                sAl[kp * 64 + sr] = lp;
            }
        }
        {
#pragma unroll
            for (int i = 0; i < 4; i++) {
                int j = tid + i * 256;
                int r2 = j >> 5;
                int cj = j & 31;
                size_t src = (size_t)(c * 32 + r2) * 64 + hf * 32 + cj;
                ((uint4*)sBh0)[j] = __ldg((const uint4*)Bh0 + src);
                ((uint4*)sBl0)[j] = __ldg((const uint4*)Bl0 + src);
                ((uint4*)sBh1)[j] = __ldg((const uint4*)Bh1 + src);
                ((uint4*)sBl1)[j] = __ldg((const uint4*)Bl1 + src);
            }
        }
        __syncthreads();

        if (c < 3 && aok) {
            const float4* pn = abase + (c + 1) * 16;
            f[0] = __ldg(pn + 0); f[1] = __ldg(pn + 1);
            f[2] = __ldg(pn + 2); f[3] = __ldg(pn + 3);
        }

#pragma unroll
        for (int ks = 0; ks < 4; ks++) {
            int kp0 = ks * 8 + (l & 3);
            int sw = (l & 3) << 3;
            uint32_t ah[2][4], al2[2][4];
#pragma unroll
            for (int mt = 0; mt < 2; mt++) {
                int r0 = wm * 32 + mt * 16 + (l >> 2);
                int i00 = kp0 * 64 + (r0 ^ sw);
                int i01 = kp0 * 64 + ((r0 + 8) ^ sw);
                int i10 = (kp0 + 4) * 64 + (r0 ^ sw);
                int i11 = (kp0 + 4) * 64 + ((r0 + 8) ^ sw);
                ah[mt][0] = sAh[i00]; ah[mt][1] = sAh[i01];
                ah[mt][2] = sAh[i10]; ah[mt][3] = sAh[i11];
                al2[mt][0] = sAl[i00]; al2[mt][1] = sAl[i01];
                al2[mt][2] = sAl[i10]; al2[mt][3] = sAl[i11];
            }
#pragma unroll
            for (int nt = 0; nt < 4; nt++) {
                int nc = wn * 32 + nt * 8 + (l >> 2);
                int nsw = nc ^ sw;
                int ix0 = kp0 * 128 + nsw;
                int ix1 = (kp0 + 4) * 128 + nsw;
                uint32_t h00 = sBh0[ix0], h01 = sBh0[ix1];
                uint32_t l00 = sBl0[ix0], l01 = sBl0[ix1];
                uint32_t h10 = sBh1[ix0], h11 = sBh1[ix1];
                uint32_t l10 = sBl1[ix0], l11 = sBl1[ix1];
#pragma unroll
                for (int mt = 0; mt < 2; mt++) {
                    mma16816(acc0[mt][nt], ah[mt], h00, h01);
                    mma16816(acc0[mt][nt], ah[mt], l00, l01);
                    mma16816(acc0[mt][nt], al2[mt], h00, h01);
                    mma16816(acc1[mt][nt], ah[mt], h10, h11);
                    mma16816(acc1[mt][nt], ah[mt], l10, l11);
                    mma16816(acc1[mt][nt], al2[mt], h10, h11);
                }
            }
        }
    }

#pragma unroll
    for (int mt = 0; mt < 2; mt++) {
        int r = rowBase + wm * 32 + mt * 16 + (l >> 2);
#pragma unroll
        for (int nt = 0; nt < 4; nt++) {
            int colb = wn * 32 + nt * 8 + 2 * (l & 3);
            float bm0 = sB0[colb], bm1 = sB0[colb + 1];
            float bs0 = sB1[colb], bs1 = sB1[colb + 1];
            int gcol = colOff + colb;
#pragma unroll
            for (int half = 0; half < 2; half++) {
                int rr = r + half * 8;
                if (rr >= M) continue;
                size_t idx = (size_t)rr * 256 + gcol;
                float m0 = acc0[mt][nt][half * 2 + 0] + bm0;
                float m1 = acc0[mt][nt][half * 2 + 1] + bm1;
                float s0 = acc1[mt][nt][half * 2 + 0] + bs0;
                float s1 = acc1[mt][nt][half * 2 + 1] + bs1;
                uint2 r0 = threefry2x32(0u, 1u, 0u, (uint32_t)idx);
                uint2 r1 = threefry2x32(0u, 1u, 0u, (uint32_t)idx + 1u);
                float z0 = m0 + expf(s0) * bits_to_eps(r0.x ^ r0.y);
                float z1 = m1 + expf(s1) * bits_to_eps(r1.x ^ r1.y);
                *(float2*)(Cmu + idx) = make_float2(m0, m1);
                *(float2*)(Cls + idx) = make_float2(s0, s1);
                *(float2*)(zOut + idx) = make_float2(z0, z1);
            }
        }
    }
}

// ---------------- launch ------------------------------------------------------
extern "C" void kernel_launch(void* const* d_in, const int* in_sizes, int n_in,
                              void* d_out, int out_size) {
    const float* x   = (const float*)d_in[0];
    const int*   ei  = (const int*)d_in[1];
    const float* W1  = (const float*)d_in[2];
    const float* b1  = (const float*)d_in[3];
    const float* Wmu = (const float*)d_in[4];
    const float* bmu = (const float*)d_in[5];
    const float* Wls = (const float*)d_in[6];
    const float* bls = (const float*)d_in[7];
    int E = in_sizes[1] / 2;

    float* out = (float*)d_out;
    float* z   = out;
    float* mu  = out + (size_t)NH;
    float* ls  = out + 2 * (size_t)NH;

    float* buf1; float* buf2; int* degp; void* bhp; void* blp;
    cudaGetSymbolAddress((void**)&buf1, g_buf1);
    cudaGetSymbolAddress((void**)&buf2, g_buf2);
    cudaGetSymbolAddress((void**)&degp, g_deg);
    cudaGetSymbolAddress(&bhp, g_Bh);
    cudaGetSymbolAddress(&blp, g_Bl);
    const uint32_t* Bh = (const uint32_t*)bhp;
    const uint32_t* Bl = (const uint32_t*)blp;

    cudaFuncSetAttribute(k_gemm_mma,
                         cudaFuncAttributeMaxDynamicSharedMemorySize, SMEM_MMA);
    cudaFuncSetAttribute(k_gemm_dual2,
                         cudaFuncAttributeMaxDynamicSharedMemorySize, SMEM_MMA);

    dim3 gspmm((N_NODES + 3) / 4);     // 2 warps per node, 4 nodes per CTA
    int cntBlks = CONV_BLKS + (E + 255) / 256;

    cudaMemsetAsync(degp, 0, N_NODES * sizeof(int));
    k_count_conv<<<cntBlks, 256>>>(ei, E, W1, Wmu, Wls);
    k_scan1<<<NB_SCAN, 1024>>>();
    k_scan2<<<NB_SCAN, 1024>>>(E);
    k_fill<<<(E + 255) / 256, 256>>>(ei, E);
    // t = A_norm @ x -> buf1
    k_spmm_csr<<<gspmm, 256>>>(x, buf1);
    // h = relu(t @ W1 + b1) -> buf2
    k_gemm_mma<<<NBLK_M, 256, SMEM_MMA>>>(buf1, N_NODES, Bh, Bl, b1, buf2);
    // p = A_norm @ h -> buf1
    k_spmm_csr<<<gspmm, 256>>>(buf2, buf1);
    // mu + ls + z in one column-split dual GEMM
    k_gemm_dual2<<<2 * NBLK_M, 256, SMEM_MMA>>>(buf1, N_NODES,
                                                Bh + 32768, Bl + 32768, bmu,
                                                Bh + 65536, Bl + 65536, bls,
                                                mu, ls, z);
}